// round 16
// baseline (speedup 1.0000x reference)
#include <cuda_runtime.h>
#include <cuda_fp16.h>
#include <cstdint>
#include <cstring>

// Problem constants
#define TPc   4
#define WSZ   16
#define B_    8
#define F_    256
#define K_    64
#define EDv   256
#define NWIN  2048
#define WTYPES 256

// Shared memory: xn buf only
#define SMEM_REQ 33792
#define BUF_SB  528       // 33x16B (odd) -> ldmatrix conflict-free

// Precomputed fragment-major operands (device globals: no allocation)
// g_WfA: Wp as mma A-fragments (M=chan). [wid(8)][ks(16)][mt(2)][lane(32)] uint4{a0..a3}
__device__ uint4 g_WfA[8 * 16 * 2 * 32];          // 128 KB
// g_Af: A_w as mma A-fragments (M=t_out). [w(256)][ks(4)][mt(4)][lane(32)] uint4
__device__ uint4 g_Af[WTYPES * 4 * 4 * 32];       // 2 MB

__device__ __forceinline__ uint32_t h2u(float a, float b) {
    __half2 h = __floats2half2_rn(a, b);
    uint32_t u;
    memcpy(&u, &h, 4);
    return u;
}

// ---------------------------------------------------------------------------
// Prep kernel:
//   blocks [0,512)    : (w, half) -> 32 rows of A[w]=deg@eb (fp32) -> g_Af frags
//   blocks [512,544)  : Wp -> g_WfA A-fragments
// ---------------------------------------------------------------------------
__global__ __launch_bounds__(256) void prep_kernel(
    const float* __restrict__ deg, const float* __restrict__ eb,
    const float* __restrict__ Wp)
{
    int tid = threadIdx.x;

    if (blockIdx.x >= 2 * WTYPES) {
        int t    = (blockIdx.x - 2 * WTYPES) * 256 + tid;   // 0..8191
        int lane = t & 31;
        int rest = t >> 5;           // 0..255
        int mt   = rest & 1;
        int ks   = (rest >> 1) & 15;
        int wid  = rest >> 5;        // 0..7
        int c0 = wid * 32 + mt * 16 + (lane >> 2);
        int k0 = ks * 16 + 2 * (lane & 3);
        uint4 u;
        u.x = h2u(Wp[c0 * 256 + k0],           Wp[c0 * 256 + k0 + 1]);
        u.y = h2u(Wp[(c0 + 8) * 256 + k0],     Wp[(c0 + 8) * 256 + k0 + 1]);
        u.z = h2u(Wp[c0 * 256 + k0 + 8],       Wp[c0 * 256 + k0 + 9]);
        u.w = h2u(Wp[(c0 + 8) * 256 + k0 + 8], Wp[(c0 + 8) * 256 + k0 + 9]);
        g_WfA[((wid * 16 + ks) * 2 + mt) * 32 + lane] = u;
        return;
    }

    __shared__ float Ds[32][64];
    __shared__ float Es[64][68];
    __shared__ float As[32][68];
    int w = blockIdx.x >> 1;
    int h = blockIdx.x & 1;
    const float* D = deg + (size_t)w * 4096 + h * 32 * 64;
    const float* E = eb  + (size_t)w * 4096;
    for (int idx = tid; idx < 2048; idx += 256)
        Ds[idx >> 6][idx & 63] = D[idx];
    for (int idx = tid; idx < 4096; idx += 256)
        Es[idx >> 6][idx & 63] = E[idx];
    __syncthreads();
    {
        int pr = tid >> 3;               // local row 0..31
        int q0 = (tid & 7) * 8;
        float acc[8];
#pragma unroll
        for (int j = 0; j < 8; j++) acc[j] = 0.f;
        for (int k = 0; k < 64; k++) {
            float a = Ds[pr][k];
#pragma unroll
            for (int j = 0; j < 8; j++) acc[j] = fmaf(a, Es[k][q0 + j], acc[j]);
        }
#pragma unroll
        for (int j = 0; j < 8; j++) As[pr][q0 + j] = acc[j];
    }
    __syncthreads();
    {
        int lane = tid & 31;
        int ks   = (tid >> 5) & 3;
        int mtl  = (tid >> 7) & 1;       // local m-tile (rows mtl*16..)
        int g = lane >> 2, q = lane & 3;
        int r0 = mtl * 16 + g;
        int k0 = ks * 16 + 2 * q;
        uint4 u;
        u.x = h2u(As[r0][k0],         As[r0][k0 + 1]);
        u.y = h2u(As[r0 + 8][k0],     As[r0 + 8][k0 + 1]);
        u.z = h2u(As[r0][k0 + 8],     As[r0][k0 + 9]);
        u.w = h2u(As[r0 + 8][k0 + 8], As[r0 + 8][k0 + 9]);
        int mt = h * 2 + mtl;            // global m-tile 0..3
        g_Af[((w * 4 + ks) * 4 + mt) * 32 + lane] = u;
    }
}

// ---------------------------------------------------------------------------
// mma / ldmatrix helpers
// ---------------------------------------------------------------------------
__device__ __forceinline__ uint32_t smem_u32(const void* p) {
    uint32_t a;
    asm("{ .reg .u64 t; cvta.to.shared.u64 t, %1; cvt.u32.u64 %0, t; }" : "=r"(a) : "l"(p));
    return a;
}

#define LDSM4(r0, r1, r2, r3, addr) \
    asm volatile("ldmatrix.sync.aligned.m8n8.x4.shared.b16 {%0,%1,%2,%3}, [%4];" \
                 : "=r"(r0), "=r"(r1), "=r"(r2), "=r"(r3) : "r"(addr))

__device__ __forceinline__ void hmma(float c[4], const uint32_t a[4],
                                     uint32_t b0, uint32_t b1) {
    asm volatile(
        "mma.sync.aligned.m16n8k16.row.col.f32.f16.f16.f32 "
        "{%0,%1,%2,%3}, {%4,%5,%6,%7}, {%8,%9}, {%0,%1,%2,%3};"
        : "+f"(c[0]), "+f"(c[1]), "+f"(c[2]), "+f"(c[3])
        : "r"(a[0]), "r"(a[1]), "r"(a[2]), "r"(a[3]), "r"(b0), "r"(b1));
}

// ---------------------------------------------------------------------------
// Fused kernel: one 256-thread CTA per window, 3 CTAs/SM (regs <= 85).
//   Register trims vs R15: LN in 2 token-batches (xv 32), GEMM1 without
//   A-frag double-buffer (Wf is L1-resident), GEMM2 split into 2 mt-halves.
//   One CTA barrier (post-LN); warps fully independent after it.
// ---------------------------------------------------------------------------
__global__ __launch_bounds__(256, 3) void fused_fp16(
    const float* __restrict__ x, const float* __restrict__ gamma,
    const float* __restrict__ beta, const float* __restrict__ bp_,
    float* __restrict__ out)
{
    extern __shared__ char smc[];
    const uint32_t buf_u = smem_u32(smc);

    const int tid  = threadIdx.x;
    const int lane = tid & 31;
    const int wid  = tid >> 5;
    const int n0   = wid * 32;       // this warp's 32 channels

    const int n   = blockIdx.x;
    const int b   = n >> 8;
    const int w   = n & 255;
    const int fi  = w >> 2;
    const int nwi = w & 3;
    const int gbase = (b * F_ + fi * TPc) * K_ + nwi * WSZ;

    // ---- single-pass LayerNorm, 2 batches of 4 tokens (register cap) ----
    {
        float gg[2][4], ee[2][4];
#pragma unroll
        for (int j = 0; j < 2; j++) {
            float4 G = *(const float4*)(gamma + 128 * j + 4 * lane);
            float4 E = *(const float4*)(beta  + 128 * j + 4 * lane);
            gg[j][0] = G.x; gg[j][1] = G.y; gg[j][2] = G.z; gg[j][3] = G.w;
            ee[j][0] = E.x; ee[j][1] = E.y; ee[j][2] = E.z; ee[j][3] = E.w;
        }
#pragma unroll
        for (int batch = 0; batch < 2; batch++) {
            float xv[4][2][4];
#pragma unroll
            for (int t4 = 0; t4 < 4; t4++) {
                int t = wid * 8 + batch * 4 + t4;
                const float* xr = x + (size_t)(gbase + (t >> 4) * K_ + (t & 15)) * EDv;
#pragma unroll
                for (int j = 0; j < 2; j++) {
                    float4 v = __ldcg((const float4*)(xr + 128 * j + 4 * lane));
                    xv[t4][j][0] = v.x; xv[t4][j][1] = v.y;
                    xv[t4][j][2] = v.z; xv[t4][j][3] = v.w;
                }
            }
#pragma unroll
            for (int t4 = 0; t4 < 4; t4++) {
                float s = 0.f, ss = 0.f;
#pragma unroll
                for (int j = 0; j < 2; j++)
#pragma unroll
                    for (int i = 0; i < 4; i++) {
                        float v = xv[t4][j][i];
                        s += v; ss = fmaf(v, v, ss);
                    }
#pragma unroll
                for (int off = 16; off >= 1; off >>= 1) {
                    s  += __shfl_xor_sync(0xffffffffu, s, off);
                    ss += __shfl_xor_sync(0xffffffffu, ss, off);
                }
                float mu   = s * (1.f / 256.f);
                float var  = ss * (1.f / 256.f) - mu * mu;
                float rstd = rsqrtf(var + 1e-5f);
                int t = wid * 8 + batch * 4 + t4;
#pragma unroll
                for (int j = 0; j < 2; j++) {
                    uint2 st;
                    st.x = h2u((xv[t4][j][0] - mu) * rstd * gg[j][0] + ee[j][0],
                               (xv[t4][j][1] - mu) * rstd * gg[j][1] + ee[j][1]);
                    st.y = h2u((xv[t4][j][2] - mu) * rstd * gg[j][2] + ee[j][2],
                               (xv[t4][j][3] - mu) * rstd * gg[j][3] + ee[j][3]);
                    *(uint2*)(smc + t * BUF_SB + 256 * j + 8 * lane) = st;
                }
            }
        }
    }
    __syncthreads();   // THE ONLY CTA BARRIER: xn visible to all warps

    const int r4 = lane >> 2, c4 = lane & 3;
    const int bnrow = ((lane >> 4) & 1) * 8 + (lane & 7);
    const int bkhi  = ((lane >> 3) & 1) * 8;

    // ---- GEMM1: y^T(256chan x 64tok) slice = Wp(A-frags LDG) @ xn^T(B LDSM) ----
    float acc1[2][8][4];
#pragma unroll
    for (int mt = 0; mt < 2; mt++)
#pragma unroll
        for (int nt = 0; nt < 8; nt++)
#pragma unroll
            for (int r = 0; r < 4; r++) acc1[mt][nt][r] = 0.f;

#pragma unroll
    for (int ks = 0; ks < 16; ks++) {
        uint32_t aC[2][4];
#pragma unroll
        for (int mt = 0; mt < 2; mt++)
            *(uint4*)aC[mt] = __ldg(g_WfA + ((wid * 16 + ks) * 2 + mt) * 32 + lane);
#pragma unroll
        for (int ntp = 0; ntp < 4; ntp++) {
            uint32_t r0, r1, r2, r3;
            uint32_t baddr = buf_u + (uint32_t)(ntp * 16 + bnrow) * BUF_SB +
                             (uint32_t)(ks * 16 + bkhi) * 2;
            LDSM4(r0, r1, r2, r3, baddr);
#pragma unroll
            for (int mt = 0; mt < 2; mt++) {
                hmma(acc1[mt][2 * ntp],     aC[mt], r0, r1);
                hmma(acc1[mt][2 * ntp + 1], aC[mt], r2, r3);
            }
        }
    }

    // ---- convert: y^T C-frags + bias -> GEMM2 B-frags (registers only) ----
    uint32_t yb[4][4][2];   // [chan-tile ntc][ks][b0,b1]
    {
        float bb[4];
#pragma unroll
        for (int ntc = 0; ntc < 4; ntc++)
            bb[ntc] = __ldg(bp_ + n0 + ntc * 8 + r4);
#pragma unroll
        for (int ntc = 0; ntc < 4; ntc++) {
            int mt1 = ntc >> 1;
            int h2i = (ntc & 1) * 2;
#pragma unroll
            for (int ks = 0; ks < 4; ks++) {
                yb[ntc][ks][0] = h2u(acc1[mt1][2 * ks][h2i]     + bb[ntc],
                                     acc1[mt1][2 * ks][h2i + 1] + bb[ntc]);
                yb[ntc][ks][1] = h2u(acc1[mt1][2 * ks + 1][h2i]     + bb[ntc],
                                     acc1[mt1][2 * ks + 1][h2i + 1] + bb[ntc]);
            }
        }
    }

    // ---- GEMM2 in two mt-halves (register cap): z = A_w(LDG frags) @ y(regs) ----
#pragma unroll
    for (int half = 0; half < 2; half++) {
        float acc2[2][4][4];
#pragma unroll
        for (int m = 0; m < 2; m++)
#pragma unroll
            for (int nt = 0; nt < 4; nt++)
#pragma unroll
                for (int r = 0; r < 4; r++) acc2[m][nt][r] = 0.f;

#pragma unroll
        for (int ks = 0; ks < 4; ks++) {
            uint32_t a2[2][4];
#pragma unroll
            for (int m = 0; m < 2; m++)
                *(uint4*)a2[m] = __ldg(
                    g_Af + (((size_t)w * 4 + ks) * 4 + half * 2 + m) * 32 + lane);
#pragma unroll
            for (int m = 0; m < 2; m++)
#pragma unroll
                for (int ntc = 0; ntc < 4; ntc++)
                    hmma(acc2[m][ntc], a2[m], yb[ntc][ks][0], yb[ntc][ks][1]);
        }

        // epilogue for this half: direct float2 scatter (window_reverse)
#pragma unroll
        for (int m = 0; m < 2; m++) {
            int mt = half * 2 + m;
            int t0 = mt * 16 + r4;
            int t1 = t0 + 8;
            float* o0 = out + (size_t)(gbase + (t0 >> 4) * K_ + (t0 & 15)) * EDv;
            float* o1 = out + (size_t)(gbase + (t1 >> 4) * K_ + (t1 & 15)) * EDv;
#pragma unroll
            for (int nt = 0; nt < 4; nt++) {
                int col = n0 + nt * 8 + 2 * c4;
                __stcg((float2*)(o0 + col),
                       make_float2(acc2[m][nt][0], acc2[m][nt][1]));
                __stcg((float2*)(o1 + col),
                       make_float2(acc2[m][nt][2], acc2[m][nt][3]));
            }
        }
    }
}

// ---------------------------------------------------------------------------
// Launch
// ---------------------------------------------------------------------------
extern "C" void kernel_launch(void* const* d_in, const int* in_sizes, int n_in,
                              void* d_out, int out_size)
{
    const float* x     = (const float*)d_in[0];
    const float* gamma = (const float*)d_in[1];
    const float* beta  = (const float*)d_in[2];
    const float* Wp    = (const float*)d_in[3];
    const float* bp    = (const float*)d_in[4];
    const float* eb    = (const float*)d_in[5];
    const float* deg   = (const float*)d_in[6];
    float* out = (float*)d_out;

    prep_kernel<<<2 * WTYPES + 32, 256>>>(deg, eb, Wp);

    cudaFuncSetAttribute(fused_fp16,
                         cudaFuncAttributeMaxDynamicSharedMemorySize, SMEM_REQ);
    fused_fp16<<<NWIN, 256, SMEM_REQ>>>(x, gamma, beta, bp, out);
}